// round 1
// baseline (speedup 1.0000x reference)
#include <cuda_runtime.h>

#define NPTS   2000000
#define NCOMP  48
#define G      300
#define STRIDE 52                     // padded row stride (floats); 52%32=20 spreads banks, 16B aligned
#define TBL    (G * STRIDE)           // 15600 floats per table
#define TBL3   (3 * TBL)              // 46800 floats total
#define SMEM_BYTES (TBL3 * 4)         // 187200 B
#define BLK    512
#define NCHUNKS ((NPTS + BLK - 1) / BLK)   // 3907
#define NBLOCKS 152                   // GB300: 152 SMs, persistent one-wave grid

// Transposed+padded tables live in device global scratch (no allocation allowed).
__device__ float g_pT[TBL3];

// Prep: transpose each param [C=48, G=300] -> [G, C(pad 52)] into g_pT.
__global__ void cp_prep(const float* __restrict__ p0,
                        const float* __restrict__ p1,
                        const float* __restrict__ p2) {
    int idx = blockIdx.x * blockDim.x + threadIdx.x;
    if (idx >= TBL3) return;
    int t   = idx / TBL;
    int rem = idx - t * TBL;
    int g   = rem / STRIDE;
    int c   = rem - g * STRIDE;
    const float* p = (t == 0) ? p0 : ((t == 1) ? p1 : p2);
    g_pT[idx] = (c < NCOMP) ? p[c * G + g] : 0.0f;
}

__global__ __launch_bounds__(BLK) void cp_eval(const float* __restrict__ xyz,
                                               float* __restrict__ out) {
    extern __shared__ float sh[];
    // Cooperative one-time table load into shared (persistent block).
    for (int i = threadIdx.x; i < TBL3; i += BLK) sh[i] = g_pT[i];
    __syncthreads();

    const float* sh0 = sh;
    const float* sh1 = sh + TBL;
    const float* sh2 = sh + 2 * TBL;

    for (int chunk = blockIdx.x; chunk < NCHUNKS; chunk += gridDim.x) {
        int n = chunk * BLK + threadIdx.x;
        if (n >= NPTS) continue;

        float x = xyz[3 * n + 0];
        float y = xyz[3 * n + 1];
        float z = xyz[3 * n + 2];

        // Match reference arithmetic order: ((coord + 1) * 0.5) * (G - 1)
        float px = (x + 1.0f) * 0.5f * (float)(G - 1);
        float py = (y + 1.0f) * 0.5f * (float)(G - 1);
        float pz = (z + 1.0f) * 0.5f * (float)(G - 1);

        int i0x = min(max((int)floorf(px), 0), G - 1);
        int i0y = min(max((int)floorf(py), 0), G - 1);
        int i0z = min(max((int)floorf(pz), 0), G - 1);
        int i1x = min(i0x + 1, G - 1);
        int i1y = min(i0y + 1, G - 1);
        int i1z = min(i0z + 1, G - 1);

        float wx = px - (float)i0x, omwx = 1.0f - wx;
        float wy = py - (float)i0y, omwy = 1.0f - wy;
        float wz = pz - (float)i0z, omwz = 1.0f - wz;

        // Row pointers; stride 52 floats = 208 B (16B aligned) -> valid float4 access.
        const float4* ax0 = (const float4*)(sh0 + i0x * STRIDE);
        const float4* ax1 = (const float4*)(sh0 + i1x * STRIDE);
        const float4* ay0 = (const float4*)(sh1 + i0y * STRIDE);
        const float4* ay1 = (const float4*)(sh1 + i1y * STRIDE);
        const float4* az0 = (const float4*)(sh2 + i0z * STRIDE);
        const float4* az1 = (const float4*)(sh2 + i1z * STRIDE);

        float* o = out + n;

        #pragma unroll
        for (int k = 0; k < NCOMP / 4; k++) {
            float4 x0 = ax0[k], x1 = ax1[k];
            float4 y0 = ay0[k], y1 = ay1[k];
            float4 z0 = az0[k], z1 = az1[k];

            float vx0 = x0.x * omwx + x1.x * wx;
            float vx1 = x0.y * omwx + x1.y * wx;
            float vx2 = x0.z * omwx + x1.z * wx;
            float vx3 = x0.w * omwx + x1.w * wx;

            float vy0 = y0.x * omwy + y1.x * wy;
            float vy1 = y0.y * omwy + y1.y * wy;
            float vy2 = y0.z * omwy + y1.z * wy;
            float vy3 = y0.w * omwy + y1.w * wy;

            float vz0 = z0.x * omwz + z1.x * wz;
            float vz1 = z0.y * omwz + z1.y * wz;
            float vz2 = z0.z * omwz + z1.z * wz;
            float vz3 = z0.w * omwz + z1.w * wz;

            o[(4 * k + 0) * NPTS] = vx0 * vy0 * vz0;
            o[(4 * k + 1) * NPTS] = vx1 * vy1 * vz1;
            o[(4 * k + 2) * NPTS] = vx2 * vy2 * vz2;
            o[(4 * k + 3) * NPTS] = vx3 * vy3 * vz3;
        }
    }
}

extern "C" void kernel_launch(void* const* d_in, const int* in_sizes, int n_in,
                              void* d_out, int out_size) {
    const float* xyz = (const float*)d_in[0];
    const float* p0  = (const float*)d_in[1];
    const float* p1  = (const float*)d_in[2];
    const float* p2  = (const float*)d_in[3];
    float* out = (float*)d_out;

    cp_prep<<<(TBL3 + 255) / 256, 256>>>(p0, p1, p2);

    static bool attr_set = false;
    if (!attr_set) {
        cudaFuncSetAttribute(cp_eval, cudaFuncAttributeMaxDynamicSharedMemorySize, SMEM_BYTES);
        attr_set = true;
    }
    cp_eval<<<NBLOCKS, BLK, SMEM_BYTES>>>(xyz, out);
}